// round 12
// baseline (speedup 1.0000x reference)
#include <cuda_runtime.h>

typedef unsigned long long ULL;

// ---------------- device scratch (no allocations allowed) ----------------
// Packed, zero-padded weights: wpad_g[lp][c] = (W_in_real[c][lp-9], W_in_imag[c][lp-9]),
// zero outside l in [0, 4086]. lp in [0, 4105).
__device__ __align__(16) float2 wpad_g[4105 * 16];
// Stage-1 partial sums: [b][s][idx]  (b:256, s:4, idx:320) = 1.3MB, L2-resident
__device__ float fpart_g[256 * 4 * 320];
// Pre-batchnorm output: [b][c*2+o]
__device__ float out_g[256 * 32];

// ---------------- packed f32x2 FMA (FFMA2) ----------------
__device__ __forceinline__ ULL fma2(ULL a, ULL b, ULL c) {
    ULL d;
    asm("fma.rn.f32x2 %0, %1, %2, %3;" : "=l"(d) : "l"(a), "l"(b), "l"(c));
    return d;
}
__device__ __forceinline__ float2 u2f2(ULL v) {
    return make_float2(__uint_as_float((unsigned)(v & 0xffffffffULL)),
                       __uint_as_float((unsigned)(v >> 32)));
}

// ---------------- kernel 0: pack + pad weights ----------------
__global__ void __launch_bounds__(1024) pack_kernel(const float* __restrict__ wr,
                                                    const float* __restrict__ wi) {
    int idx = blockIdx.x * blockDim.x + threadIdx.x;
    if (idx >= 4105 * 16) return;
    int lp = idx >> 4;
    int c  = idx & 15;
    int l  = lp - 9;
    float2 v = make_float2(0.f, 0.f);
    if (l >= 0 && l < 4087) {
        v.x = wr[c * 4087 + l];
        v.y = wi[c * 4087 + l];
    }
    wpad_g[lp * 16 + c] = v;
}

// ---------------- kernel 1: depthwise sliding filters (stage 1) ----------------
// grid (256 batches, 4 segments), 256 threads = 16 channels x 16 j-chunks.
// Thread (c,j): contiguous 64-position run, 8 chunks of 8 with BOTH the x
// values and the weight values prefetched 8-deep (MLP 16, nothing latency-
// critical inside the chunk). No barriers until the epilogue reduce.
// f[b,w,c] = sum_p x[b,p,c] * Wpad[p + 9 - w]
__global__ void __launch_bounds__(256) stage1_kernel(const float* __restrict__ x) {
    __shared__ float red[8][320];      // 10.2KB: per-warp partials

    int b    = blockIdx.x;
    int s    = blockIdx.y;             // 0..3
    int tid  = threadIdx.x;
    int c    = tid & 15;
    int j    = tid >> 4;               // 0..15
    int p0   = s * 1024 + j * 64;
    int warp = tid >> 5;               // 0..7

    const ULL* xp = (const ULL*)x + ((size_t)b * 4096 + p0) * 16 + c;
    const ULL* wp = (const ULL*)wpad_g + (size_t)p0 * 16 + c;   // wp[k*16] = Wpad[p0+k]

    // rotating window: slot m%10 holds Wpad[p0+m]; preload m = 0..8
    ULL wbuf[10];
#pragma unroll
    for (int k = 0; k < 9; k++) wbuf[k] = wp[(size_t)k * 16];

    ULL acc[10];
#pragma unroll
    for (int w = 0; w < 10; w++) acc[w] = 0ULL;

    // 8 chunks of 8 positions; x AND weight loads batched up front (MLP 16)
#pragma unroll
    for (int ch = 0; ch < 8; ch++) {
        ULL xv[8], wv[8];
#pragma unroll
        for (int u = 0; u < 8; u++) {
            xv[u] = xp[(size_t)(ch * 8 + u) * 16];
            wv[u] = wp[(size_t)(ch * 8 + u + 9) * 16];    // Wpad[p0+t+9]
        }
#pragma unroll
        for (int u = 0; u < 8; u++) {
            int t = ch * 8 + u;
            wbuf[(t + 9) % 10] = wv[u];
#pragma unroll
            for (int w = 0; w < 10; w++)
                acc[w] = fma2(xv[u], wbuf[(t + 9 - w) % 10], acc[w]);   // Wpad[p+9-w]
        }
    }

    // combine j-pair within warp (lane L with L^16); lanes 0-15 store
#pragma unroll
    for (int w = 0; w < 10; w++) {
        float2 f = u2f2(acc[w]);
        f.x += __shfl_xor_sync(0xffffffffu, f.x, 16);
        f.y += __shfl_xor_sync(0xffffffffu, f.y, 16);
        if ((tid & 16) == 0) {
            red[warp][(c * 10 + w) * 2 + 0] = f.x;
            red[warp][(c * 10 + w) * 2 + 1] = f.y;
        }
    }
    __syncthreads();

    // reduce 8 warp-rows over 320 entries, write fpart[b][s]
    for (int idx = tid; idx < 320; idx += 256) {
        float v = 0.f;
#pragma unroll
        for (int ww = 0; ww < 8; ww++) v += red[ww][idx];
        fpart_g[((size_t)b * 4 + s) * 320 + idx] = v;
    }
}

// ---------------- kernel 2: amp + Linear(2C->2) + out filter ----------------
// one block per b, 320 threads; fpart is tiny and L2-hot, read directly.
__global__ void __launch_bounds__(320) stage23_kernel(const float* __restrict__ Wnl,
                                                      const float* __restrict__ WoR,
                                                      const float* __restrict__ WoI) {
    __shared__ float tf[10][32];       // [w][i], i<16: amp*fr, i>=16: amp*fi
    __shared__ float contrib[10][32];  // [w][c*2+o]

    int b = blockIdx.x;
    int tid = threadIdx.x;

    // reduce over s=4 directly from L2; idx = (c*10+w)*2+o = tid (coalesced)
    {
        const float* fp = fpart_g + (size_t)b * 4 * 320 + tid;
        float v = fp[0] + fp[320] + fp[640] + fp[960];
        float other = __shfl_xor_sync(0xffffffffu, v, 1);
        float amp = v * v + other * other;
        int pair = tid >> 1;          // c*10 + w
        int o    = tid & 1;
        int cc   = pair / 10;
        int w    = pair - cc * 10;
        tf[w][cc + 16 * o] = amp * v; // o=0: amp*fr ; o=1: amp*fi
    }
    __syncthreads();

    // per-channel Linear(2C->2) + output-filter weighting
    {
        int w = tid >> 5;
        int q = tid & 31;
        int cc = q >> 1;
        int o  = q & 1;
        float acc = 0.f;
        const float* wn = Wnl + (cc * 2 + o) * 32;
#pragma unroll
        for (int i = 0; i < 32; i++) acc += tf[w][i] * wn[i];
        float wo = (o == 0 ? WoR : WoI)[cc * 10 + w];
        contrib[w][q] = acc * wo;
    }
    __syncthreads();

    // sum over w, write pre-BN output
    if (tid < 32) {
        float ssum = 0.f;
#pragma unroll
        for (int ww = 0; ww < 10; ww++) ssum += contrib[ww][tid];
        out_g[b * 32 + tid] = ssum;
    }
}

// ---------------- kernel 3: BatchNorm1d (training stats), 1 block ----------------
__global__ void __launch_bounds__(512) bn_kernel(const float* __restrict__ gamma,
                                                 const float* __restrict__ beta,
                                                 float* __restrict__ out) {
    __shared__ float bnbuf[32][257];   // [q = ch*2+o][b], padded rows

    int tid = threadIdx.x;
    for (int i = tid; i < 8192; i += 512) {
        int bb = i >> 5;
        int q  = i & 31;
        bnbuf[q][bb] = out_g[i];
    }
    __syncthreads();

    // one warp per channel
    int ch = tid >> 5, lane = tid & 31;
    float s1 = 0.f;
#pragma unroll
    for (int j = 0; j < 8; j++) {
        int bb = lane + j * 32;
        s1 += bnbuf[2 * ch][bb] + bnbuf[2 * ch + 1][bb];
    }
#pragma unroll
    for (int off = 16; off; off >>= 1) s1 += __shfl_xor_sync(0xffffffffu, s1, off);
    float mean = s1 * (1.f / 512.f);

    float s2 = 0.f;
#pragma unroll
    for (int j = 0; j < 8; j++) {
        int bb = lane + j * 32;
        float d0 = bnbuf[2 * ch][bb] - mean;
        float d1 = bnbuf[2 * ch + 1][bb] - mean;
        s2 += d0 * d0 + d1 * d1;
    }
#pragma unroll
    for (int off = 16; off; off >>= 1) s2 += __shfl_xor_sync(0xffffffffu, s2, off);
    float inv = rsqrtf(s2 * (1.f / 512.f) + 1e-5f);

    float g = gamma[ch], bb_ = beta[ch];
#pragma unroll
    for (int j = 0; j < 8; j++) {
        int bb = lane + j * 32;
        out[bb * 32 + 2 * ch]     = (bnbuf[2 * ch][bb] - mean) * inv * g + bb_;
        out[bb * 32 + 2 * ch + 1] = (bnbuf[2 * ch + 1][bb] - mean) * inv * g + bb_;
    }
}

// ---------------- launch ----------------
extern "C" void kernel_launch(void* const* d_in, const int* in_sizes, int n_in,
                              void* d_out, int out_size) {
    const float* x     = (const float*)d_in[0];
    const float* wir   = (const float*)d_in[1];
    const float* wii   = (const float*)d_in[2];
    const float* wnl   = (const float*)d_in[3];
    const float* wor   = (const float*)d_in[4];
    const float* woi   = (const float*)d_in[5];
    const float* gamma = (const float*)d_in[6];
    const float* beta  = (const float*)d_in[7];
    float* out = (float*)d_out;

    pack_kernel<<<(4105 * 16 + 1023) / 1024, 1024>>>(wir, wii);
    stage1_kernel<<<dim3(256, 4), 256>>>(x);
    stage23_kernel<<<256, 320>>>(wnl, wor, woi);
    bn_kernel<<<1, 512>>>(gamma, beta, out);
}